// round 1
// baseline (speedup 1.0000x reference)
#include <cuda_runtime.h>
#include <mma.h>
#include <math.h>

using namespace nvcuda;

// ---------------- problem constants ----------------
#define BATCH   2
#define LIN     135000
#define DMODEL  768
#define NLAYERS 24
#define DINNER  1536
#define DSTATE  16
#define DCONV   4
#define DTRANK  48
#define KDS     32
#define SDS     32
#define LATENT  64
#define LSEQ    4218                 // (135000-32)/32 + 1
#define MREAL   (BATCH*LSEQ)         // 8436
#define MPAD    8448                 // 66 * 128

// ---------------- scratch (device globals; no allocation allowed) ----------------
__device__ float g_h    [MPAD*DMODEL];
__device__ float g_hn   [MPAD*DMODEL];
__device__ float g_xz   [MPAD*2*DINNER];
__device__ float g_u    [MPAD*DINNER];
__device__ float g_delta[MPAD*DINNER];
__device__ float g_draw [MPAD*DINNER];   // dt raw, then delta*u (in place)
__device__ float g_proj [MPAD*80];
__device__ float g_y    [MPAD*DINNER];
__device__ float g_pooled[BATCH*DMODEL];

// ---------------- downsample conv: x(2,1,135000) -> h(MREAL,768) ----------------
__global__ void k_downsample(const float* __restrict__ x, const float* __restrict__ cw,
                             const float* __restrict__ cb, float* __restrict__ h) {
    int r = blockIdx.x;                 // token row
    int b = r / LSEQ, t = r % LSEQ;
    __shared__ float xs[KDS];
    if (threadIdx.x < KDS) xs[threadIdx.x] = x[b*LIN + t*SDS + threadIdx.x];
    __syncthreads();
    for (int n = threadIdx.x; n < DMODEL; n += blockDim.x) {
        float acc = cb[n];
        const float* w = cw + n*KDS;
        #pragma unroll
        for (int k = 0; k < KDS; k++) acc += xs[k]*w[k];
        h[r*DMODEL + n] = acc;
    }
}

// ---------------- RMSNorm over 768 ----------------
__global__ void k_rmsnorm(const float* __restrict__ in, const float* __restrict__ w,
                          float* __restrict__ out) {
    int r = blockIdx.x;
    __shared__ float red[256];
    const float* row = in + r*DMODEL;
    float s = 0.f;
    #pragma unroll
    for (int i = 0; i < 3; i++) { float v = row[threadIdx.x + i*256]; s += v*v; }
    red[threadIdx.x] = s; __syncthreads();
    for (int o = 128; o > 0; o >>= 1) {
        if (threadIdx.x < o) red[threadIdx.x] += red[threadIdx.x + o];
        __syncthreads();
    }
    float inv = rsqrtf(red[0]/(float)DMODEL + 1e-5f);
    #pragma unroll
    for (int i = 0; i < 3; i++) {
        int d = threadIdx.x + i*256;
        out[r*DMODEL + d] = row[d]*inv*w[d];
    }
}

// ---------------- generic TF32 wmma GEMM: C[M,N] = A[M,K] * W[N,K]^T (+C) ----------------
#define BM 128
#define BN 64
#define BK 32
#define SLD 36          // smem row stride for A/W tiles (36 floats = 144B, mult of 16B)
#define CLD 68          // smem row stride for C staging

__global__ __launch_bounds__(256) void k_gemm_tf32(
    const float* __restrict__ A, int lda,
    const float* __restrict__ W, int ldw,
    float*       __restrict__ C, int ldc,
    int N, int K, int acc)
{
    __shared__ float smem[128*CLD];          // 34.8 KB, aliased: [A|W] tiles then C stage
    float* As = smem;                        // [128][SLD]
    float* Ws = smem + BM*SLD;               // [64][SLD]

    int tid    = threadIdx.x;
    int warpId = tid >> 5;
    int mw = warpId & 3;                     // 4 warps along M
    int nw = warpId >> 2;                    // 2 warps along N
    int rowBase = blockIdx.y * BM;
    int n0      = blockIdx.x * BN;

    wmma::fragment<wmma::accumulator,16,16,8,float> cf[2][2];
    #pragma unroll
    for (int i = 0; i < 2; i++)
        #pragma unroll
        for (int j = 0; j < 2; j++) wmma::fill_fragment(cf[i][j], 0.f);

    int ktiles = (K + BK - 1)/BK;
    for (int kt = 0; kt < ktiles; kt++) {
        int k0 = kt*BK;
        #pragma unroll
        for (int i = 0; i < 16; i++) {       // A tile 128x32
            int idx = tid + i*256;
            int r = idx >> 5, c = idx & 31;
            int k = k0 + c;
            As[r*SLD + c] = (k < K) ? A[(rowBase + r)*lda + k] : 0.f;
        }
        #pragma unroll
        for (int i = 0; i < 8; i++) {        // W tile 64x32
            int idx = tid + i*256;
            int r = idx >> 5, c = idx & 31;
            int k = k0 + c, n = n0 + r;
            Ws[r*SLD + c] = (k < K && n < N) ? W[n*ldw + k] : 0.f;
        }
        __syncthreads();

        #pragma unroll
        for (int kk = 0; kk < BK; kk += 8) {
            wmma::fragment<wmma::matrix_a,16,16,8,wmma::precision::tf32,wmma::row_major> af[2];
            wmma::fragment<wmma::matrix_b,16,16,8,wmma::precision::tf32,wmma::col_major> bf[2];
            #pragma unroll
            for (int i = 0; i < 2; i++) {
                wmma::load_matrix_sync(af[i], As + (mw*32 + i*16)*SLD + kk, SLD);
                #pragma unroll
                for (int e = 0; e < af[i].num_elements; e++)
                    af[i].x[e] = wmma::__float_to_tf32(af[i].x[e]);
            }
            #pragma unroll
            for (int j = 0; j < 2; j++) {
                wmma::load_matrix_sync(bf[j], Ws + (nw*32 + j*16)*SLD + kk, SLD);
                #pragma unroll
                for (int e = 0; e < bf[j].num_elements; e++)
                    bf[j].x[e] = wmma::__float_to_tf32(bf[j].x[e]);
            }
            #pragma unroll
            for (int i = 0; i < 2; i++)
                #pragma unroll
                for (int j = 0; j < 2; j++)
                    wmma::mma_sync(cf[i][j], af[i], bf[j], cf[i][j]);
        }
        __syncthreads();
    }

    // epilogue through smem so ragged N (80) can be masked and residual-add fused
    float* Cs = smem;
    #pragma unroll
    for (int i = 0; i < 2; i++)
        #pragma unroll
        for (int j = 0; j < 2; j++)
            wmma::store_matrix_sync(Cs + (mw*32 + i*16)*CLD + (nw*32 + j*16),
                                    cf[i][j], CLD, wmma::mem_row_major);
    __syncthreads();
    #pragma unroll
    for (int i = 0; i < 32; i++) {
        int idx = tid + i*256;
        int r = idx >> 6, c = idx & 63;
        int n = n0 + c;
        if (n < N) {
            int g = (rowBase + r)*ldc + n;
            float v = Cs[r*CLD + c];
            if (acc) v += C[g];
            C[g] = v;
        }
    }
}

// ---------------- causal depthwise conv1d (width 4) + silu on u half of xz ----------------
__global__ void k_conv1d_silu(const float* __restrict__ xz, const float* __restrict__ w,
                              const float* __restrict__ bias, float* __restrict__ u) {
    int idx = blockIdx.x*blockDim.x + threadIdx.x;
    const int D4 = DINNER/4;
    if (idx >= MREAL*D4) return;
    int r  = idx / D4;
    int d4 = (idx % D4)*4;
    int t  = r % LSEQ;
    float4 acc = make_float4(bias[d4], bias[d4+1], bias[d4+2], bias[d4+3]);
    #pragma unroll
    for (int j = 0; j < DCONV; j++) {
        int tt = t + j - (DCONV-1);
        if (tt < 0) continue;
        float4 v = *(const float4*)(xz + (r + j - (DCONV-1))*(2*DINNER) + d4);
        acc.x += v.x * w[(d4+0)*DCONV + j];
        acc.y += v.y * w[(d4+1)*DCONV + j];
        acc.z += v.z * w[(d4+2)*DCONV + j];
        acc.w += v.w * w[(d4+3)*DCONV + j];
    }
    acc.x = acc.x / (1.f + __expf(-acc.x));
    acc.y = acc.y / (1.f + __expf(-acc.y));
    acc.z = acc.z / (1.f + __expf(-acc.z));
    acc.w = acc.w / (1.f + __expf(-acc.w));
    *(float4*)(u + r*DINNER + d4) = acc;
}

// ---------------- delta = softplus(draw + b); draw <- delta * u ----------------
__global__ void k_delta(float* __restrict__ draw, const float* __restrict__ db,
                        const float* __restrict__ u, float* __restrict__ delta) {
    int idx = blockIdx.x*blockDim.x + threadIdx.x;
    if (idx >= MREAL*DINNER) return;
    int d = idx % DINNER;
    float v  = draw[idx] + db[d];
    float dl = (v > 20.f) ? v : log1pf(expf(v));
    delta[idx] = dl;
    draw[idx]  = dl * u[idx];
}

// ---------------- selective scan: 16 lanes per (b,d) chain ----------------
__global__ void k_scan(const float* __restrict__ delta, const float* __restrict__ du,
                       const float* __restrict__ proj,  const float* __restrict__ u,
                       const float* __restrict__ xz,    const float* __restrict__ Alog,
                       const float* __restrict__ Dskip, float* __restrict__ y) {
    int chain = blockIdx.x*(blockDim.x/16) + (threadIdx.x >> 4);
    int s = threadIdx.x & 15;
    int b = chain / DINNER, d = chain % DINNER;
    float Av = -expf(Alog[d*DSTATE + s]);
    float Dv = Dskip[d];
    bool lane0 = (s == 0);
    float h = 0.f;
    int rbase = b*LSEQ;

    int t = 0;
    for (; t + 4 <= LSEQ; t += 4) {
        float dl[4], db_[4], bv[4], cv[4], uv[4], zv[4];
        #pragma unroll
        for (int j = 0; j < 4; j++) {
            int r = rbase + t + j;
            dl[j]  = delta[r*DINNER + d];
            db_[j] = du  [r*DINNER + d];
            bv[j]  = proj[r*80 + 48 + s];
            cv[j]  = proj[r*80 + 64 + s];
            if (lane0) {
                uv[j] = u [r*DINNER + d];
                zv[j] = xz[r*2*DINNER + DINNER + d];
            }
        }
        #pragma unroll
        for (int j = 0; j < 4; j++) {
            h = __expf(dl[j]*Av)*h + db_[j]*bv[j];
            float yv = h*cv[j];
            yv += __shfl_xor_sync(0xffffffffu, yv, 8);
            yv += __shfl_xor_sync(0xffffffffu, yv, 4);
            yv += __shfl_xor_sync(0xffffffffu, yv, 2);
            yv += __shfl_xor_sync(0xffffffffu, yv, 1);
            if (lane0) {
                float z = zv[j];
                float sig = 1.f/(1.f + __expf(-z));
                y[(rbase + t + j)*DINNER + d] = (yv + uv[j]*Dv) * z * sig;
            }
        }
    }
    for (; t < LSEQ; t++) {
        int r = rbase + t;
        float dl  = delta[r*DINNER + d];
        float db_ = du  [r*DINNER + d];
        float bv  = proj[r*80 + 48 + s];
        float cv  = proj[r*80 + 64 + s];
        h = __expf(dl*Av)*h + db_*bv;
        float yv = h*cv;
        yv += __shfl_xor_sync(0xffffffffu, yv, 8);
        yv += __shfl_xor_sync(0xffffffffu, yv, 4);
        yv += __shfl_xor_sync(0xffffffffu, yv, 2);
        yv += __shfl_xor_sync(0xffffffffu, yv, 1);
        if (lane0) {
            float uvv = u [r*DINNER + d];
            float z   = xz[r*2*DINNER + DINNER + d];
            float sig = 1.f/(1.f + __expf(-z));
            y[r*DINNER + d] = (yv + uvv*Dv) * z * sig;
        }
    }
}

// ---------------- final pooling + head ----------------
__global__ void k_zero(float* p, int n) {
    int i = blockIdx.x*blockDim.x + threadIdx.x;
    if (i < n) p[i] = 0.f;
}

__global__ void k_pool(const float* __restrict__ hn, float* __restrict__ pooled) {
    int d  = blockIdx.x*blockDim.x + threadIdx.x;   // gridDim.x = 3 -> 768
    int b  = blockIdx.y;
    int tc = blockIdx.z;                            // 32 chunks
    int t0 = tc*132, t1 = t0 + 132; if (t1 > LSEQ) t1 = LSEQ;
    float acc = 0.f;
    for (int t = t0; t < t1; t++) acc += hn[(b*LSEQ + t)*DMODEL + d];
    atomicAdd(&pooled[b*DMODEL + d], acc);
}

__global__ void k_head(const float* __restrict__ pooled, const float* __restrict__ pw,
                       const float* __restrict__ pb, const float* __restrict__ lw,
                       const float* __restrict__ lb, float* __restrict__ out) {
    int b = blockIdx.x, j = threadIdx.x;            // 64 threads
    __shared__ float zs[LATENT];
    const float* pr = pooled + b*DMODEL;
    const float* wr = pw + j*DMODEL;
    float acc = 0.f;
    for (int d = 0; d < DMODEL; d++) acc += pr[d]*wr[d];
    float zed = acc*(1.f/(float)LSEQ) + pb[j];
    zs[j] = zed; __syncthreads();
    float mu = 0.f;
    for (int i = 0; i < LATENT; i++) mu += zs[i];
    mu /= LATENT;
    float var = 0.f;
    for (int i = 0; i < LATENT; i++) { float dd = zs[i]-mu; var += dd*dd; }
    var /= LATENT;
    out[b*LATENT + j] = (zed - mu)*rsqrtf(var + 1e-5f)*lw[j] + lb[j];
}

// ---------------- host orchestration ----------------
static inline void launch_gemm(const float* A, int lda, const float* W, int ldw,
                               float* C, int ldc, int N, int K, int acc) {
    dim3 g((N + BN - 1)/BN, MPAD/BM);
    k_gemm_tf32<<<g, 256>>>(A, lda, W, ldw, C, ldc, N, K, acc);
}

extern "C" void kernel_launch(void* const* d_in, const int* in_sizes, int n_in,
                              void* d_out, int out_size) {
    const float* x         = (const float*)d_in[0];
    const float* conv_w    = (const float*)d_in[1];
    const float* conv_b    = (const float*)d_in[2];
    const float* norm_w    = (const float*)d_in[3];
    const float* in_proj_w = (const float*)d_in[4];
    const float* conv1d_w  = (const float*)d_in[5];
    const float* conv1d_b  = (const float*)d_in[6];
    const float* x_proj_w  = (const float*)d_in[7];
    const float* dt_proj_w = (const float*)d_in[8];
    const float* dt_proj_b = (const float*)d_in[9];
    const float* A_log     = (const float*)d_in[10];
    const float* D_skip    = (const float*)d_in[11];
    const float* out_proj_w= (const float*)d_in[12];
    const float* norm_f_w  = (const float*)d_in[13];
    const float* proj_w    = (const float*)d_in[14];
    const float* proj_b    = (const float*)d_in[15];
    const float* ln_w      = (const float*)d_in[16];
    const float* ln_b      = (const float*)d_in[17];

    float *h, *hn, *xz, *u, *delta, *draw, *proj, *y, *pooled;
    cudaGetSymbolAddress((void**)&h,      g_h);
    cudaGetSymbolAddress((void**)&hn,     g_hn);
    cudaGetSymbolAddress((void**)&xz,     g_xz);
    cudaGetSymbolAddress((void**)&u,      g_u);
    cudaGetSymbolAddress((void**)&delta,  g_delta);
    cudaGetSymbolAddress((void**)&draw,   g_draw);
    cudaGetSymbolAddress((void**)&proj,   g_proj);
    cudaGetSymbolAddress((void**)&y,      g_y);
    cudaGetSymbolAddress((void**)&pooled, g_pooled);

    k_downsample<<<MREAL, 128>>>(x, conv_w, conv_b, h);

    const int convThreads = 256;
    const int convBlocks  = (MREAL*(DINNER/4) + convThreads - 1)/convThreads;
    const int ewBlocks    = (MREAL*DINNER + 255)/256;

    for (int l = 0; l < NLAYERS; l++) {
        k_rmsnorm<<<MREAL, 256>>>(h, norm_w + (size_t)l*DMODEL, hn);
        launch_gemm(hn, DMODEL, in_proj_w + (size_t)l*2*DINNER*DMODEL, DMODEL,
                    xz, 2*DINNER, 2*DINNER, DMODEL, 0);
        k_conv1d_silu<<<convBlocks, convThreads>>>(xz, conv1d_w + (size_t)l*DINNER*DCONV,
                                                   conv1d_b + (size_t)l*DINNER, u);
        launch_gemm(u, DINNER, x_proj_w + (size_t)l*80*DINNER, DINNER,
                    proj, 80, 80, DINNER, 0);
        launch_gemm(proj, 80, dt_proj_w + (size_t)l*DINNER*DTRANK, DTRANK,
                    draw, DINNER, DINNER, DTRANK, 0);
        k_delta<<<ewBlocks, 256>>>(draw, dt_proj_b + (size_t)l*DINNER, u, delta);
        k_scan<<<(BATCH*DINNER)/8, 128>>>(delta, draw, proj, u, xz,
                                          A_log + (size_t)l*DINNER*DSTATE,
                                          D_skip + (size_t)l*DINNER, y);
        launch_gemm(y, DINNER, out_proj_w + (size_t)l*DMODEL*DINNER, DINNER,
                    h, DMODEL, DMODEL, DINNER, 1);
    }

    k_rmsnorm<<<MREAL, 256>>>(h, norm_f_w, hn);
    k_zero<<<(BATCH*DMODEL + 255)/256, 256>>>(pooled, BATCH*DMODEL);
    k_pool<<<dim3(3, BATCH, 32), 256>>>(hn, pooled);
    k_head<<<BATCH, LATENT>>>(pooled, proj_w, proj_b, ln_w, ln_b, (float*)d_out);
}